// round 2
// baseline (speedup 1.0000x reference)
#include <cuda_runtime.h>
#include <cuda_bf16.h>
#include <math.h>

// Problem constants
#define BB 64      // batch
#define TT 256     // time
#define DD 512     // input dim
#define HH 1024    // hidden
#define G3 3072    // 3*H
#define G2 2048    // 2*H
#define KSA 4      // K-split for h@Wh^T  (1024/4 = 256 per chunk)
#define KSC 8      // K-split for rh@Wc^T (1024/8 = 128 per chunk)
#define NB 128     // persistent CTAs
#define NTH 256    // threads per CTA

// ---------------- scratch (device globals; no allocs allowed) ----------------
__device__ float g_ig[(size_t)TT * BB * G3];     // [T][B][3H] precomputed input gates
__device__ float g_p[BB * G3];                   // [B][3H] peephole gates
__device__ float g_h[2 * BB * HH];               // ping-pong hidden state
__device__ float g_rh[BB * HH];                  // resetgate * h
__device__ float g_gi[BB * HH];                  // inputgate
__device__ float g_part1[KSA * BB * G2];         // split-K partials for h@Wh^T
__device__ float g_part2[KSC * BB * HH];         // split-K partials for rh@Wc^T

// ---------------- software grid barrier ----------------
__device__ unsigned g_barcnt = 0;
__device__ volatile unsigned g_bargen = 0;

__device__ __forceinline__ void grid_sync() {
    __syncthreads();
    if (threadIdx.x == 0) {
        __threadfence();
        unsigned g0 = g_bargen;
        unsigned arrived = atomicAdd(&g_barcnt, 1);
        if (arrived == NB - 1) {
            g_barcnt = 0;
            __threadfence();
            g_bargen = g0 + 1;
        } else {
            while (g_bargen == g0) { }
        }
        __threadfence();
    }
    __syncthreads();
}

// ---------------- tiled SGEMM with bias (standalone, for ig and p) -----------
// C[m][n] = A_row(m) . W[n] + bias[n].  BM=BN=64, BK=16, 256 threads, 4x4 tile.
// xmap!=0: m = t*B + b maps to x row (b*T + t).
__global__ void gemm_bias_kernel(const float* __restrict__ A, const float* __restrict__ W,
                                 const float* __restrict__ bias, float* __restrict__ C,
                                 int K, int N, int xmap)
{
    __shared__ float As[64][17];
    __shared__ float Bs[64][17];
    int tid = threadIdx.x;
    int tx = tid & 15, ty = tid >> 4;
    int m0 = blockIdx.y * 64;
    int n0 = blockIdx.x * 64;
    int lr = tid >> 2;
    int lk = (tid & 3) * 4;

    size_t arow;
    {
        int m = m0 + lr;
        if (xmap) {
            int t = m >> 6;
            int b = m & 63;
            arow = ((size_t)b * TT + t) * (size_t)K;
        } else {
            arow = (size_t)m * K;
        }
    }
    size_t brow = (size_t)(n0 + lr) * K;

    float acc[4][4] = {};
    for (int k0 = 0; k0 < K; k0 += 16) {
        float4 va = *reinterpret_cast<const float4*>(A + arow + k0 + lk);
        As[lr][lk] = va.x; As[lr][lk+1] = va.y; As[lr][lk+2] = va.z; As[lr][lk+3] = va.w;
        float4 vb = *reinterpret_cast<const float4*>(W + brow + k0 + lk);
        Bs[lr][lk] = vb.x; Bs[lr][lk+1] = vb.y; Bs[lr][lk+2] = vb.z; Bs[lr][lk+3] = vb.w;
        __syncthreads();
        #pragma unroll
        for (int k = 0; k < 16; k++) {
            float a[4], bv[4];
            #pragma unroll
            for (int i = 0; i < 4; i++) a[i]  = As[ty + 16*i][k];
            #pragma unroll
            for (int j = 0; j < 4; j++) bv[j] = Bs[tx + 16*j][k];
            #pragma unroll
            for (int i = 0; i < 4; i++)
                #pragma unroll
                for (int j = 0; j < 4; j++)
                    acc[i][j] += a[i] * bv[j];
        }
        __syncthreads();
    }
    #pragma unroll
    for (int i = 0; i < 4; i++) {
        int m = m0 + ty + 16*i;
        #pragma unroll
        for (int j = 0; j < 4; j++) {
            int n = n0 + tx + 16*j;
            C[(size_t)m * N + n] = acc[i][j] + bias[n];
        }
    }
}

// ---------------- in-kernel 64x64 GEMM tile over one K-chunk -----------------
__device__ __forceinline__ void gemm_tile(const float* __restrict__ A,
                                          const float* __restrict__ W,
                                          float* __restrict__ Cp,
                                          int N, int n0, int ksIdx, int k0, int KCH,
                                          float As[64][17], float Bs[64][17])
{
    int tid = threadIdx.x;
    int tx = tid & 15, ty = tid >> 4;
    int lr = tid >> 2;
    int lk = (tid & 3) * 4;

    const float* arow = A + (size_t)lr * HH + k0;
    const float* brow = W + (size_t)(n0 + lr) * HH + k0;

    float acc[4][4] = {};
    for (int kk = 0; kk < KCH; kk += 16) {
        float4 va = *reinterpret_cast<const float4*>(arow + kk + lk);
        As[lr][lk] = va.x; As[lr][lk+1] = va.y; As[lr][lk+2] = va.z; As[lr][lk+3] = va.w;
        float4 vb = *reinterpret_cast<const float4*>(brow + kk + lk);
        Bs[lr][lk] = vb.x; Bs[lr][lk+1] = vb.y; Bs[lr][lk+2] = vb.z; Bs[lr][lk+3] = vb.w;
        __syncthreads();
        #pragma unroll
        for (int k = 0; k < 16; k++) {
            float a[4], bv[4];
            #pragma unroll
            for (int i = 0; i < 4; i++) a[i]  = As[ty + 16*i][k];
            #pragma unroll
            for (int j = 0; j < 4; j++) bv[j] = Bs[tx + 16*j][k];
            #pragma unroll
            for (int i = 0; i < 4; i++)
                #pragma unroll
                for (int j = 0; j < 4; j++)
                    acc[i][j] += a[i] * bv[j];
        }
        __syncthreads();
    }
    size_t base = (size_t)ksIdx * 64;
    #pragma unroll
    for (int i = 0; i < 4; i++) {
        int m = ty + 16*i;
        #pragma unroll
        for (int j = 0; j < 4; j++) {
            int n = n0 + tx + 16*j;
            Cp[(base + m) * (size_t)N + n] = acc[i][j];
        }
    }
}

// ---------------- persistent scan kernel ----------------
__global__ void __launch_bounds__(NTH, 1)
scan_kernel(const float* __restrict__ h0,
            const float* __restrict__ Wh, const float* __restrict__ bh,
            const float* __restrict__ Wc, const float* __restrict__ bc,
            float* __restrict__ out, int want_hT)
{
    __shared__ float As[64][17];
    __shared__ float Bs[64][17];

    const int job  = blockIdx.x;            // 0..127
    const int gtid = blockIdx.x * NTH + threadIdx.x;   // 0..32767

    for (int t = 0; t < TT; t++) {
        const float* hcur = (t == 0) ? h0 : (g_h + (size_t)(t & 1) * (BB * HH));
        float* hnext = g_h + (size_t)((t + 1) & 1) * (BB * HH);
        const float* igt = g_ig + (size_t)t * BB * G3;

        // ---- Phase A: part1 = h @ Wh^T (32 tiles x splitK 4) ----
        {
            int tile = job >> 2;       // 0..31
            int ks   = job & 3;        // 0..3
            gemm_tile(hcur, Wh, g_part1, G2, tile * 64, ks, ks * 256, 256, As, Bs);
        }
        grid_sync();

        // ---- Phase B: gates r,i; rh = r*h; gi ----
        #pragma unroll
        for (int it = 0; it < 2; it++) {
            int idx = gtid + it * (NB * NTH);
            int b = idx >> 10, j = idx & 1023;
            float hr = bh[j], hi = bh[HH + j];
            #pragma unroll
            for (int ks = 0; ks < KSA; ks++) {
                const float* row = g_part1 + (size_t)(ks * BB + b) * G2;
                hr += row[j];
                hi += row[HH + j];
            }
            size_t bg = (size_t)b * G3;
            float xr = igt[bg + j]      + g_p[bg + j];
            float xi = igt[bg + HH + j] + g_p[bg + HH + j];
            float r  = 1.0f / (1.0f + expf(-(xr + hr)));
            float ii = 1.0f / (1.0f + expf(-(xi + hi)));
            g_rh[idx] = r * hcur[idx];
            g_gi[idx] = ii;
        }
        grid_sync();

        // ---- Phase C: part2 = rh @ Wc^T (16 tiles x splitK 8) ----
        {
            int tile = job >> 3;       // 0..15
            int ks   = job & 7;        // 0..7
            gemm_tile(g_rh, Wc, g_part2, HH, tile * 64, ks, ks * 128, 128, As, Bs);
        }
        grid_sync();

        // ---- Phase D: newgate, blend, write out + hnext ----
        #pragma unroll
        for (int it = 0; it < 2; it++) {
            int idx = gtid + it * (NB * NTH);
            int b = idx >> 10, j = idx & 1023;
            float hn = bc[j];
            #pragma unroll
            for (int ks = 0; ks < KSC; ks++)
                hn += g_part2[(size_t)(ks * BB + b) * HH + j];
            size_t bg = (size_t)b * G3;
            float n = tanhf(igt[bg + G2 + j] + hn + g_p[bg + G2 + j]);
            float hc = hcur[idx];
            float hy = hc + g_gi[idx] * (n - hc);
            hnext[idx] = hy;
            out[((size_t)b * TT + t) * HH + j] = hy;
            if (want_hT && t == TT - 1)
                out[(size_t)BB * TT * HH + idx] = hy;
        }
        grid_sync();
    }
}

// ---------------- launch ----------------
extern "C" void kernel_launch(void* const* d_in, const int* in_sizes, int n_in,
                              void* d_out, int out_size)
{
    const float* x   = (const float*)d_in[0];
    const float* h0  = (const float*)d_in[1];
    const float* ctx = (const float*)d_in[2];
    const float* Wi  = (const float*)d_in[3];
    const float* bi  = (const float*)d_in[4];
    const float* Wh  = (const float*)d_in[5];
    const float* bh  = (const float*)d_in[6];
    const float* Wp  = (const float*)d_in[7];
    const float* bp  = (const float*)d_in[8];
    const float* Wc  = (const float*)d_in[9];
    const float* bc  = (const float*)d_in[10];
    float* out = (float*)d_out;

    float *p_ig, *p_p;
    cudaGetSymbolAddress((void**)&p_ig, g_ig);
    cudaGetSymbolAddress((void**)&p_p,  g_p);

    // ig_all[t][b][:] = x[b][t][:] @ Wi^T + bi   (time-major)
    gemm_bias_kernel<<<dim3(G3/64, (TT*BB)/64), 256>>>(x, Wi, bi, p_ig, DD, G3, 1);

    // p[b][:] = ctx[b] @ Wp^T + bp
    gemm_bias_kernel<<<dim3(G3/64, 1), 256>>>(ctx, Wp, bp, p_p, HH, G3, 0);

    const int want_hT = (out_size >= (int)((size_t)BB*TT*HH + BB*HH)) ? 1 : 0;

    // persistent scan: entire 256-step recurrence in one launch
    scan_kernel<<<NB, NTH>>>(h0, Wh, bh, Wc, bc, out, want_hT);
}

// round 3
// speedup vs baseline: 1.7722x; 1.7722x over previous
#include <cuda_runtime.h>
#include <cuda_bf16.h>
#include <math.h>

// Problem constants
#define BB 64      // batch
#define TT 256     // time
#define DD 512     // input dim
#define HH 1024    // hidden
#define G3 3072    // 3*H
#define G2 2048    // 2*H
#define KSA 4      // K-split for h@Wh^T  (1024/4 = 256 per chunk)
#define KSC 8      // K-split for rh@Wc^T (1024/8 = 128 per chunk)
#define NB 128     // persistent CTAs
#define NTH 256    // threads per CTA

// ---------------- scratch (device globals; no allocs allowed) ----------------
__device__ float g_ig[(size_t)TT * BB * G3];     // [T][B][3H] precomputed input gates
__device__ float g_p[BB * G3];                   // [B][3H] peephole gates
__device__ float g_h[2 * BB * HH];               // ping-pong hidden state
__device__ float g_rh[BB * HH];                  // resetgate * h
__device__ float g_gi[BB * HH];                  // inputgate
__device__ float g_part1[KSA * BB * G2];         // split-K partials for h@Wh^T
__device__ float g_part2[KSC * BB * HH];         // split-K partials for rh@Wc^T
// tf32-rounded weights
__device__ float g_Wi_t[G3 * DD];
__device__ float g_Wh_t[G2 * HH];
__device__ float g_Wc_t[HH * HH];
__device__ float g_Wp_t[G3 * HH];

// ---------------- tf32 helpers ----------------
__device__ __forceinline__ unsigned f2tf32(float f) {
    unsigned u;
    asm("cvt.rna.tf32.f32 %0, %1;" : "=r"(u) : "f"(f));
    return u;
}

__device__ __forceinline__ void mma_tf32(float c[4],
                                         unsigned a0, unsigned a1, unsigned a2, unsigned a3,
                                         unsigned b0, unsigned b1)
{
    asm volatile("mma.sync.aligned.m16n8k8.row.col.f32.tf32.tf32.f32 "
                 "{%0,%1,%2,%3},{%4,%5,%6,%7},{%8,%9},{%0,%1,%2,%3};"
                 : "+f"(c[0]), "+f"(c[1]), "+f"(c[2]), "+f"(c[3])
                 : "r"(a0), "r"(a1), "r"(a2), "r"(a3), "r"(b0), "r"(b1));
}

// ---------------- weight rounding prologue ----------------
__global__ void round_tf32_kernel(const float* __restrict__ src, float* __restrict__ dst, int n)
{
    int i = blockIdx.x * 256 + threadIdx.x;
    if (i < n) dst[i] = __uint_as_float(f2tf32(src[i]));
}

// ---------------- software grid barrier ----------------
__device__ unsigned g_barcnt = 0;
__device__ volatile unsigned g_bargen = 0;

__device__ __forceinline__ void grid_sync() {
    __syncthreads();
    if (threadIdx.x == 0) {
        __threadfence();
        unsigned g0 = g_bargen;
        unsigned arrived = atomicAdd(&g_barcnt, 1);
        if (arrived == NB - 1) {
            g_barcnt = 0;
            __threadfence();
            g_bargen = g0 + 1;
        } else {
            while (g_bargen == g0) { }
        }
        __threadfence();
    }
    __syncthreads();
}

// ---------------- 64x32 smem staging (256 threads) ----------------
// src points at element [row 0][col 0] of the 64x32 slab; row stride = rstride.
template<bool CVT>
__device__ __forceinline__ void stage64x32(const float* __restrict__ src, size_t rstride,
                                           float dst[64][36], int tid)
{
    int r = tid >> 3;
    int c = (tid & 7) * 4;
    #pragma unroll
    for (int hh = 0; hh < 2; hh++) {
        float4 v = *reinterpret_cast<const float4*>(src + (size_t)(r + 32 * hh) * rstride + c);
        if (CVT) {
            v.x = __uint_as_float(f2tf32(v.x));
            v.y = __uint_as_float(f2tf32(v.y));
            v.z = __uint_as_float(f2tf32(v.z));
            v.w = __uint_as_float(f2tf32(v.w));
        }
        *reinterpret_cast<float4*>(&dst[r + 32 * hh][c]) = v;
    }
}

// ---------------- inner mma over a 64x64x32 slab ----------------
__device__ __forceinline__ void mma_block(const float As[64][36], const float Ws[64][36],
                                          float acc[4][4], int wr, int wc, int grp, int qd)
{
    #pragma unroll
    for (int k8 = 0; k8 < 4; k8++) {
        int kb = k8 * 8;
        unsigned a0 = __float_as_uint(As[16 * wr + grp    ][kb + qd    ]);
        unsigned a1 = __float_as_uint(As[16 * wr + grp + 8][kb + qd    ]);
        unsigned a2 = __float_as_uint(As[16 * wr + grp    ][kb + qd + 4]);
        unsigned a3 = __float_as_uint(As[16 * wr + grp + 8][kb + qd + 4]);
        #pragma unroll
        for (int j = 0; j < 4; j++) {
            int nl = 32 * wc + 8 * j + grp;
            unsigned b0 = __float_as_uint(Ws[nl][kb + qd    ]);
            unsigned b1 = __float_as_uint(Ws[nl][kb + qd + 4]);
            mma_tf32(acc[j], a0, a1, a2, a3, b0, b1);
        }
    }
}

// ---------------- standalone mma GEMM with bias (ig, p) ----------------
// C[m][n] = A_row(m) . Wt[n] + bias[n].  Wt pre-rounded tf32.  64x64 CTA tile.
// xmap!=0: m = t*B + b maps to A row (b*T + t)  (time-major out from [B,T,K] input).
__global__ void __launch_bounds__(NTH)
mma_gemm_bias(const float* __restrict__ A, const float* __restrict__ Wt,
              const float* __restrict__ bias, float* __restrict__ C,
              int K, int N, int xmap)
{
    __shared__ float As[64][36];
    __shared__ float Ws[64][36];
    int tid = threadIdx.x;
    int wid = tid >> 5, lane = tid & 31;
    int wr = wid & 3, wc = wid >> 2;
    int grp = lane >> 2, qd = lane & 3;
    int m0 = blockIdx.y * 64;
    int n0 = blockIdx.x * 64;

    // A row base for this thread's staging rows (r and r+32)
    size_t arow[2];
    {
        int r = tid >> 3;
        #pragma unroll
        for (int hh = 0; hh < 2; hh++) {
            int m = m0 + r + 32 * hh;
            if (xmap) {
                int t = m >> 6, b = m & 63;
                arow[hh] = ((size_t)b * TT + t) * (size_t)K;
            } else {
                arow[hh] = (size_t)m * K;
            }
        }
    }

    float acc[4][4] = {};
    int c = (tid & 7) * 4;

    for (int k0 = 0; k0 < K; k0 += 32) {
        // stage A (cvt) with custom row mapping
        #pragma unroll
        for (int hh = 0; hh < 2; hh++) {
            float4 v = *reinterpret_cast<const float4*>(A + arow[hh] + k0 + c);
            v.x = __uint_as_float(f2tf32(v.x));
            v.y = __uint_as_float(f2tf32(v.y));
            v.z = __uint_as_float(f2tf32(v.z));
            v.w = __uint_as_float(f2tf32(v.w));
            *reinterpret_cast<float4*>(&As[(tid >> 3) + 32 * hh][c]) = v;
        }
        // stage W (pre-rounded)
        stage64x32<false>(Wt + (size_t)n0 * K + k0, K, Ws, tid);
        __syncthreads();
        mma_block(As, Ws, acc, wr, wc, grp, qd);
        __syncthreads();
    }

    // epilogue: C[m][n] = acc + bias[n]
    #pragma unroll
    for (int half = 0; half < 2; half++) {
        int m = m0 + 16 * wr + grp + 8 * half;
        #pragma unroll
        for (int j = 0; j < 4; j++) {
            int n = n0 + 32 * wc + 8 * j + 2 * qd;
            float2 v;
            v.x = acc[j][2 * half + 0] + bias[n];
            v.y = acc[j][2 * half + 1] + bias[n + 1];
            *reinterpret_cast<float2*>(&C[(size_t)m * N + n]) = v;
        }
    }
}

// ---------------- in-scan 64x64 mma tile over one K-chunk ----------------
__device__ __forceinline__ void gemm_tile_mma(const float* __restrict__ A,
                                              const float* __restrict__ Wt,
                                              float* __restrict__ Cp,
                                              int N, int n0, int ksIdx, int k0, int KCH,
                                              float As[64][36], float Ws[64][36])
{
    int tid = threadIdx.x;
    int wid = tid >> 5, lane = tid & 31;
    int wr = wid & 3, wc = wid >> 2;
    int grp = lane >> 2, qd = lane & 3;

    float acc[4][4] = {};

    for (int kk = 0; kk < KCH; kk += 32) {
        stage64x32<true >(A  + (size_t)0 * HH + k0 + kk, HH, As, tid);
        stage64x32<false>(Wt + (size_t)n0 * HH + k0 + kk, HH, Ws, tid);
        __syncthreads();
        mma_block(As, Ws, acc, wr, wc, grp, qd);
        __syncthreads();
    }

    size_t base = (size_t)ksIdx * 64;
    #pragma unroll
    for (int half = 0; half < 2; half++) {
        int m = 16 * wr + grp + 8 * half;
        #pragma unroll
        for (int j = 0; j < 4; j++) {
            int n = n0 + 32 * wc + 8 * j + 2 * qd;
            float2 v;
            v.x = acc[j][2 * half + 0];
            v.y = acc[j][2 * half + 1];
            *reinterpret_cast<float2*>(&Cp[(base + m) * (size_t)N + n]) = v;
        }
    }
}

// ---------------- persistent scan kernel ----------------
__global__ void __launch_bounds__(NTH, 1)
scan_kernel(const float* __restrict__ h0,
            const float* __restrict__ bh,
            const float* __restrict__ bc,
            float* __restrict__ out, int want_hT)
{
    __shared__ float As[64][36];
    __shared__ float Ws[64][36];

    const int job  = blockIdx.x;                         // 0..127
    const int gtid = blockIdx.x * NTH + threadIdx.x;     // 0..32767

    for (int t = 0; t < TT; t++) {
        const float* hcur = (t == 0) ? h0 : (g_h + (size_t)(t & 1) * (BB * HH));
        float* hnext = g_h + (size_t)((t + 1) & 1) * (BB * HH);
        const float* igt = g_ig + (size_t)t * BB * G3;

        // ---- Phase A: part1 = h @ Wh^T (32 tiles x splitK 4) ----
        {
            int tile = job >> 2;       // 0..31
            int ks   = job & 3;        // 0..3
            gemm_tile_mma(hcur, g_Wh_t, g_part1, G2, tile * 64, ks, ks * 256, 256, As, Ws);
        }
        grid_sync();

        // ---- Phase B: gates r,i; rh = r*h; gi ----
        #pragma unroll
        for (int it = 0; it < 2; it++) {
            int idx = gtid + it * (NB * NTH);
            int b = idx >> 10, j = idx & 1023;
            float hr = bh[j], hi = bh[HH + j];
            #pragma unroll
            for (int ks = 0; ks < KSA; ks++) {
                const float* row = g_part1 + (size_t)(ks * BB + b) * G2;
                hr += row[j];
                hi += row[HH + j];
            }
            size_t bg = (size_t)b * G3;
            float xr = igt[bg + j]      + g_p[bg + j];
            float xi = igt[bg + HH + j] + g_p[bg + HH + j];
            float r  = 1.0f / (1.0f + expf(-(xr + hr)));
            float ii = 1.0f / (1.0f + expf(-(xi + hi)));
            g_rh[idx] = r * hcur[idx];
            g_gi[idx] = ii;
        }
        grid_sync();

        // ---- Phase C: part2 = rh @ Wc^T (16 tiles x splitK 8) ----
        {
            int tile = job >> 3;       // 0..15
            int ks   = job & 7;        // 0..7
            gemm_tile_mma(g_rh, g_Wc_t, g_part2, HH, tile * 64, ks, ks * 128, 128, As, Ws);
        }
        grid_sync();

        // ---- Phase D: newgate, blend, write out + hnext ----
        #pragma unroll
        for (int it = 0; it < 2; it++) {
            int idx = gtid + it * (NB * NTH);
            int b = idx >> 10, j = idx & 1023;
            float hn = bc[j];
            #pragma unroll
            for (int ks = 0; ks < KSC; ks++)
                hn += g_part2[(size_t)(ks * BB + b) * HH + j];
            size_t bg = (size_t)b * G3;
            float n = tanhf(igt[bg + G2 + j] + hn + g_p[bg + G2 + j]);
            float hc = hcur[idx];
            float hy = hc + g_gi[idx] * (n - hc);
            hnext[idx] = hy;
            out[((size_t)b * TT + t) * HH + j] = hy;
            if (want_hT && t == TT - 1)
                out[(size_t)BB * TT * HH + idx] = hy;
        }
        grid_sync();
    }
}

// ---------------- launch ----------------
extern "C" void kernel_launch(void* const* d_in, const int* in_sizes, int n_in,
                              void* d_out, int out_size)
{
    const float* x   = (const float*)d_in[0];
    const float* h0  = (const float*)d_in[1];
    const float* ctx = (const float*)d_in[2];
    const float* Wi  = (const float*)d_in[3];
    const float* bi  = (const float*)d_in[4];
    const float* Wh  = (const float*)d_in[5];
    const float* bh  = (const float*)d_in[6];
    const float* Wp  = (const float*)d_in[7];
    const float* bp  = (const float*)d_in[8];
    const float* Wc  = (const float*)d_in[9];
    const float* bc  = (const float*)d_in[10];
    float* out = (float*)d_out;

    float *p_ig, *p_p, *p_Wi, *p_Wh, *p_Wc, *p_Wp;
    cudaGetSymbolAddress((void**)&p_ig, g_ig);
    cudaGetSymbolAddress((void**)&p_p,  g_p);
    cudaGetSymbolAddress((void**)&p_Wi, g_Wi_t);
    cudaGetSymbolAddress((void**)&p_Wh, g_Wh_t);
    cudaGetSymbolAddress((void**)&p_Wc, g_Wc_t);
    cudaGetSymbolAddress((void**)&p_Wp, g_Wp_t);

    // prologue: round weights to tf32
    round_tf32_kernel<<<(G3 * DD + 255) / 256, 256>>>(Wi, p_Wi, G3 * DD);
    round_tf32_kernel<<<(G2 * HH + 255) / 256, 256>>>(Wh, p_Wh, G2 * HH);
    round_tf32_kernel<<<(HH * HH + 255) / 256, 256>>>(Wc, p_Wc, HH * HH);
    round_tf32_kernel<<<(G3 * HH + 255) / 256, 256>>>(Wp, p_Wp, G3 * HH);

    // ig_all[t][b][:] = x[b][t][:] @ Wi^T + bi   (time-major)
    mma_gemm_bias<<<dim3(G3 / 64, (TT * BB) / 64), NTH>>>(x, p_Wi, bi, p_ig, DD, G3, 1);

    // p[b][:] = ctx[b] @ Wp^T + bp
    mma_gemm_bias<<<dim3(G3 / 64, 1), NTH>>>(ctx, p_Wp, bp, p_p, HH, G3, 0);

    const int want_hT = (out_size >= (int)((size_t)BB * TT * HH + BB * HH)) ? 1 : 0;

    // persistent scan: entire 256-step recurrence in one launch
    scan_kernel<<<NB, NTH>>>(h0, bh, bc, out, want_hT);
}